// round 16
// baseline (speedup 1.0000x reference)
#include <cuda_runtime.h>
#include <cuda_fp16.h>
#include <cstdint>

#define B_  16
#define N_  512
#define T_  64
#define OC_ 64

// ---------------- scratch (device globals; no runtime allocation) ----------
__device__ __align__(16) float  g_norm  [N_ * N_];      // fp32 row-normalized adj
__device__ __align__(16) float  g_norm2f[N_ * N_];      // fp32 norm^2
__device__ __align__(16) int8_t g_normq [N_ * N_];      // int8 [i][j]
__device__ __align__(16) int8_t g_norm2q[N_ * N_];      // int8 [i][j]
__device__ __align__(16) __half g_Z1h[B_ * OC_ * N_ * T_];   // [boc][j][t] fp16
__device__ __align__(16) __half g_Z2h[B_ * OC_ * N_ * T_];
__device__ __align__(16) int8_t g_Z1q[B_ * OC_ * N_ * T_];   // [boc][t][j] int8
__device__ __align__(16) int8_t g_Z2q[B_ * OC_ * N_ * T_];
__device__ __align__(16) float  g_zs[1024 * 64];        // per-(boc,t) Z scale
__device__ __align__(16) __half g_Whf[192 * 64];        // [gc][c] fp16
__device__ unsigned g_maxn_bits;                        // max(norm, norm2) as bits

// ======================= helpers ===========================================
__device__ __forceinline__ uint32_t smem_u32(const void* p) {
    uint32_t a;
    asm("{ .reg .u64 t; cvta.to.shared.u64 t, %1; cvt.u32.u64 %0, t; }"
        : "=r"(a) : "l"(p));
    return a;
}

#define CP16(dst, src) \
    asm volatile("cp.async.cg.shared.global [%0], [%1], 16;" \
                 :: "r"(dst), "l"(src) : "memory")
#define CP_COMMIT()  asm volatile("cp.async.commit_group;" ::: "memory")
#define CP_WAIT1()   asm volatile("cp.async.wait_group 1;" ::: "memory")
#define CP_WAIT0()   asm volatile("cp.async.wait_group 0;" ::: "memory")

#define MMA_F16(c, a0, a1, a2, a3, b0, b1) \
    asm volatile("mma.sync.aligned.m16n8k16.row.col.f32.f16.f16.f32 " \
                 "{%0,%1,%2,%3}, {%4,%5,%6,%7}, {%8,%9}, {%0,%1,%2,%3};" \
                 : "+f"((c)[0]), "+f"((c)[1]), "+f"((c)[2]), "+f"((c)[3]) \
                 : "r"(a0), "r"(a1), "r"(a2), "r"(a3), "r"(b0), "r"(b1))

#define MMA_S8(c, a0, a1, a2, a3, b0, b1) \
    asm volatile("mma.sync.aligned.m16n8k32.row.col.s32.s8.s8.s32 " \
                 "{%0,%1,%2,%3}, {%4,%5,%6,%7}, {%8,%9}, {%0,%1,%2,%3};" \
                 : "+r"((c)[0]), "+r"((c)[1]), "+r"((c)[2]), "+r"((c)[3]) \
                 : "r"(a0), "r"(a1), "r"(a2), "r"(a3), "r"(b0), "r"(b1))

__device__ __forceinline__ void ldsm_x4(uint32_t* r, uint32_t addr) {
    asm volatile("ldmatrix.sync.aligned.m8n8.x4.shared.b16 {%0,%1,%2,%3}, [%4];"
                 : "=r"(r[0]), "=r"(r[1]), "=r"(r[2]), "=r"(r[3]) : "r"(addr));
}
__device__ __forceinline__ void ldsm_x4t(uint32_t* r, uint32_t addr) {
    asm volatile("ldmatrix.sync.aligned.m8n8.x4.trans.shared.b16 {%0,%1,%2,%3}, [%4];"
                 : "=r"(r[0]), "=r"(r[1]), "=r"(r[2]), "=r"(r[3]) : "r"(addr));
}

__device__ __forceinline__ int8_t q8(float v, float inv) {
    int q = __float2int_rn(v * inv);
    q = max(-127, min(127, q));
    return (int8_t)q;
}

// ---------------- kernel 0a: row-normalized adjacency (+W convert, +max) ---
__global__ void k_rownorm(const float* __restrict__ adj,
                          const float* __restrict__ W) {
    const int i = blockIdx.x;
    __shared__ float red[256];
    float s = 0.f;
    for (int j = threadIdx.x; j < N_; j += 256) s += adj[i * N_ + j];
    red[threadIdx.x] = s;
    __syncthreads();
    for (int off = 128; off > 0; off >>= 1) {
        if (threadIdx.x < off) red[threadIdx.x] += red[threadIdx.x + off];
        __syncthreads();
    }
    const float inv = 1.0f / (red[0] + 1e-6f);
    __syncthreads();
    float vmax = 0.f;
    for (int j = threadIdx.x; j < N_; j += 256) {
        const float v = adj[i * N_ + j] * inv;
        g_norm[i * N_ + j] = v;
        vmax = fmaxf(vmax, v);
    }
    red[threadIdx.x] = vmax;
    __syncthreads();
    for (int off = 128; off > 0; off >>= 1) {
        if (threadIdx.x < off) red[threadIdx.x] = fmaxf(red[threadIdx.x], red[threadIdx.x + off]);
        __syncthreads();
    }
    if (threadIdx.x == 0) atomicMax(&g_maxn_bits, __float_as_uint(red[0]));
    // fused W -> fp16 [gc][c]
    if (i < 48) {
        const int idx = i * 256 + threadIdx.x;
        const int gc = idx >> 6, c = idx & 63;
        const int grp = gc >> 6, oc = gc & 63;
        g_Whf[idx] = __float2half_rn(W[oc * 192 + grp * 64 + c]);
    }
}

// ---------------- kernel 0b: norm2 = norm @ norm (fp32 store, +max) --------
__global__ void k_norm2() {
    __shared__ float As[16][16];
    __shared__ float Bs[16][17];
    __shared__ float rmx[256];
    const int i = blockIdx.y * 16 + threadIdx.y;
    const int j = blockIdx.x * 16 + threadIdx.x;
    float acc = 0.f;
    for (int k0 = 0; k0 < N_; k0 += 16) {
        As[threadIdx.y][threadIdx.x] = g_norm[i * N_ + k0 + threadIdx.x];
        Bs[threadIdx.y][threadIdx.x] = g_norm[(k0 + threadIdx.y) * N_ + j];
        __syncthreads();
#pragma unroll
        for (int k = 0; k < 16; k++) acc += As[threadIdx.y][k] * Bs[k][threadIdx.x];
        __syncthreads();
    }
    g_norm2f[i * N_ + j] = acc;
    const int t2 = threadIdx.y * 16 + threadIdx.x;
    rmx[t2] = acc;
    __syncthreads();
    for (int off = 128; off > 0; off >>= 1) {
        if (t2 < off) rmx[t2] = fmaxf(rmx[t2], rmx[t2 + off]);
        __syncthreads();
    }
    if (t2 == 0) atomicMax(&g_maxn_bits, __float_as_uint(rmx[0]));
}

// ---------------- kernel 0c: quantize norm/norm2 to int8 --------------------
__global__ void k_nq() {
    const int i = blockIdx.x;
    const float mx = __uint_as_float(g_maxn_bits);
    const float inv = (mx > 0.f) ? 127.f / mx : 0.f;
    for (int j = threadIdx.x; j < N_; j += 256) {
        g_normq [i * N_ + j] = q8(g_norm  [i * N_ + j], inv);
        g_norm2q[i * N_ + j] = q8(g_norm2f[i * N_ + j], inv);
    }
}

// ---------------- kernel 1: channel mix via fp16 tensor cores ---------------
// EXACT R8 configuration (measured 97us). fp32 accum, two-pass epilogue.
#define XHST 264
#define WHST 72
#define SST  260
#define MIX_SMEM 49920

__global__ __launch_bounds__(256, 2) void k_mix_f16(const float* __restrict__ x,
                                                    const float* __restrict__ bias,
                                                    float* __restrict__ out) {
    extern __shared__ char dsm[];
    __half* Xh = (__half*)dsm;                       // [c=64][m=256]
    const uint32_t sb = smem_u32(dsm);
    const uint32_t wOff = 64 * XHST * 2;             // 33792
    const int n0 = blockIdx.x * 4, cn = blockIdx.y, b = blockIdx.z;
    const int tid = threadIdx.x, wid = tid >> 5, lane = tid & 31;
    const int u = wid >> 2, wi = wid & 3;
    const int g = lane >> 2, tg = lane & 3;
    const int q = lane >> 3, rr = lane & 7;

#pragma unroll
    for (int r = 0; r < 3; r++) {
        const int i = r * 256 + tid;
        const int gcr = i >> 3, qq = i & 7;
        CP16(sb + wOff + (uint32_t)(gcr * WHST + qq * 8) * 2,
             g_Whf + (cn * 96 + gcr) * 64 + qq * 8);
    }
    CP_COMMIT();

#pragma unroll
    for (int r = 0; r < 16; r++) {
        const int i = r * 256 + tid;
        const int c = i >> 6, chunk = i & 63;
        const int nl = chunk >> 4, tq = chunk & 15;
        const float4 v = *(const float4*)(x + ((b * 64 + c) * 512 + n0 + nl) * 64 + tq * 4);
        union { __half2 h[2]; uint2 u2; } cv;
        cv.h[0] = __floats2half2_rn(v.x, v.y);
        cv.h[1] = __floats2half2_rn(v.z, v.w);
        *(uint2*)(Xh + c * XHST + nl * 64 + tq * 4) = cv.u2;
    }

    float acc[4][6][4];
#pragma unroll
    for (int mt = 0; mt < 4; mt++)
#pragma unroll
        for (int nt = 0; nt < 6; nt++)
#pragma unroll
            for (int r = 0; r < 4; r++) acc[mt][nt][r] = 0.f;

    CP_WAIT0();
    __syncthreads();

#pragma unroll
    for (int ks = 0; ks < 4; ks++) {
        uint32_t bf[3][4];
#pragma unroll
        for (int ntp = 0; ntp < 3; ntp++) {
            const int rowB = u * 48 + ntp * 16 + (q >> 1) * 8 + rr;
            const int colB = ks * 16 + (q & 1) * 8;
            ldsm_x4(bf[ntp], sb + wOff + (uint32_t)(rowB * WHST + colB) * 2);
        }
#pragma unroll
        for (int mt = 0; mt < 4; mt++) {
            const int rowA = ks * 16 + (q >> 1) * 8 + rr;
            const int colA = wi * 64 + mt * 16 + (q & 1) * 8;
            uint32_t af[4];
            ldsm_x4t(af, sb + (uint32_t)(rowA * XHST + colA) * 2);
#pragma unroll
            for (int nt = 0; nt < 6; nt++)
                MMA_F16(acc[mt][nt], af[0], af[1], af[2], af[3],
                        bf[nt >> 1][(nt & 1) * 2], bf[nt >> 1][(nt & 1) * 2 + 1]);
        }
    }

    float* Ss = (float*)dsm;
#pragma unroll
    for (int up = 0; up < 2; up++) {
        __syncthreads();
        if (u == up) {
#pragma unroll
            for (int mt = 0; mt < 4; mt++) {
                const int row = wi * 64 + mt * 16 + g;
#pragma unroll
                for (int nt = 0; nt < 6; nt++) {
                    const int col = nt * 8 + tg * 2;
                    Ss[col * SST + row]           = acc[mt][nt][0];
                    Ss[(col + 1) * SST + row]     = acc[mt][nt][1];
                    Ss[col * SST + row + 8]       = acc[mt][nt][2];
                    Ss[(col + 1) * SST + row + 8] = acc[mt][nt][3];
                }
            }
        }
        __syncthreads();
#pragma unroll
        for (int r = 0; r < 12; r++) {
            const int idx = r * 256 + tid;
            const int ocl = idx >> 6, mq = idx & 63;
            float4 v = *(const float4*)(Ss + ocl * SST + mq * 4);
            const int gc = cn * 96 + up * 48 + ocl;
            const int grp = gc >> 6, oc = gc & 63;
            const int base = ((b * 64 + oc) * 512 + n0 + (mq >> 4)) * 64 + (mq & 15) * 4;
            if (grp == 0) {
                const float bv = __ldg(bias + oc);
                v.x += bv; v.y += bv; v.z += bv; v.w += bv;
                *(float4*)(out + base) = v;
            } else {
                __half* dst = (grp == 1) ? g_Z1h : g_Z2h;
                union { __half2 h[2]; uint2 u2; } cv;
                cv.h[0] = __floats2half2_rn(v.x, v.y);
                cv.h[1] = __floats2half2_rn(v.z, v.w);
                *(uint2*)(dst + base) = cv.u2;
            }
        }
    }
}

// ---------------- kernel 1b: Z quantize + transpose to [t][j] int8 ----------
// CTA per (b,oc) plane pair. smem planes [j][t], stride 68 halves (136B,
// 8B-aligned so the uint2 fill stores are legal — the R14 crash was ZJST=66).
#define ZJST 68
#define ZQ_PLANES (2 * 512 * ZJST * 2)              // 139264
#define ZQ_SMEM (ZQ_PLANES + 1024 + 256)            // 140544

__global__ __launch_bounds__(256, 1) void k_zq() {
    extern __shared__ char zsm[];
    __half* buf  = (__half*)zsm;                      // 2 x 512 x 68
    float* red   = (float*)(zsm + ZQ_PLANES);
    float* invs  = (float*)(zsm + ZQ_PLANES + 1024);
    const int boc = blockIdx.x, tid = threadIdx.x;

#pragma unroll
    for (int pl = 0; pl < 2; pl++) {
        const uint2* src = (const uint2*)((pl ? g_Z2h : g_Z1h) + (size_t)boc * 32768);
        for (int r = 0; r < 32; r++) {
            const int idx = r * 256 + tid;
            const int j = idx >> 4, tq = idx & 15;
            *(uint2*)(buf + pl * (512 * ZJST) + j * ZJST + tq * 4) = src[idx];
        }
    }
    __syncthreads();

    // per-column (t) max over j, both planes
    {
        const int t = tid & 63, part = tid >> 6;
        float m = 0.f;
        for (int j = part; j < 512; j += 4) {
            m = fmaxf(m, fabsf(__half2float(buf[j * ZJST + t])));
            m = fmaxf(m, fabsf(__half2float(buf[512 * ZJST + j * ZJST + t])));
        }
        red[tid] = m;
    }
    __syncthreads();
    if (tid < 64) {
        const float mx = fmaxf(fmaxf(red[tid], red[tid + 64]),
                               fmaxf(red[tid + 128], red[tid + 192]));
        g_zs[boc * 64 + tid] = (mx > 0.f) ? mx / 127.f : 1.f;
        invs[tid] = (mx > 0.f) ? 127.f / mx : 0.f;
    }
    __syncthreads();

    // quantize + transpose: thread (t, seg of 128 j)
    const int tt = tid >> 2, seg = tid & 3;
    const float inv = invs[tt];
#pragma unroll
    for (int pl = 0; pl < 2; pl++) {
        int8_t* dst = (pl ? g_Z2q : g_Z1q) + (size_t)boc * 32768 + tt * 512;
        const __half* bsrc = buf + pl * (512 * ZJST);
#pragma unroll
        for (int blk = 0; blk < 8; blk++) {
            const int j0 = seg * 128 + blk * 16;
            uint32_t w[4];
#pragma unroll
            for (int wq = 0; wq < 4; wq++) {
                uint32_t pk = 0;
#pragma unroll
                for (int e = 0; e < 4; e++) {
                    const float v = __half2float(bsrc[(j0 + wq * 4 + e) * ZJST + tt]);
                    pk |= (uint32_t)(uint8_t)q8(v, inv) << (e * 8);
                }
                w[wq] = pk;
            }
            uint4 o; o.x = w[0]; o.y = w[1]; o.z = w[2]; o.w = w[3];
            *(uint4*)(dst + j0) = o;
        }
    }
}

// ---------------- kernel 2: out += norm@Z1 + norm2@Z2 (int8 IMMA) ----------
// CTA = 128i x 64t x 2oc, 256 thr / 8 warps, 2 CTAs/SM, Kc=32 (1 k32-step).
// A = normq [i][j] int8; B = Zq [t][j] int8. Plain LDS.32 frags, 48B strides.
#define ASTQ 48
#define A_SECQ (128 * ASTQ)            // 6144 per matrix
#define A_BYTESQ (2 * A_SECQ)          // 12288
#define B_SECQ (64 * ASTQ)             // 3072 per plane
#define STAGEQ (A_BYTESQ + 4 * B_SECQ) // 24576
#define NCHUNKQ 16

__global__ __launch_bounds__(256, 2) void k_spmm_i8(float* __restrict__ out) {
    extern __shared__ char sm[];
    const uint32_t sb = smem_u32(sm);
    const int tid = threadIdx.x, wid = tid >> 5, lane = tid & 31;
    const int ih = blockIdx.x, ocp = blockIdx.y, b = blockIdx.z;
    const int i0g = ih * 128, oc0 = ocp * 2;
    const int wi = wid & 1, u = wid >> 1;
    const int ocl = u >> 1, th = u & 1;
    const int g = lane >> 2, tg = lane & 3;

    const int8_t* zbq[4];
    zbq[0] = g_Z1q + (size_t)(b * 64 + oc0) * 32768;
    zbq[1] = g_Z2q + (size_t)(b * 64 + oc0) * 32768;
    zbq[2] = g_Z1q + (size_t)(b * 64 + oc0 + 1) * 32768;
    zbq[3] = g_Z2q + (size_t)(b * 64 + oc0 + 1) * 32768;

    // per-thread dequant scales (per t column)
    const float sn = __uint_as_float(g_maxn_bits) / 127.f;
    const float* zsp = g_zs + (b * 64 + oc0 + ocl) * 64;
    float zsv[4][2];
#pragma unroll
    for (int nt = 0; nt < 4; nt++) {
        const int t0 = th * 32 + nt * 8 + tg * 2;
        zsv[nt][0] = sn * __ldg(zsp + t0);
        zsv[nt][1] = sn * __ldg(zsp + t0 + 1);
    }

    int acc[4][4][4];
#pragma unroll
    for (int mt = 0; mt < 4; mt++)
#pragma unroll
        for (int nt = 0; nt < 4; nt++)
#pragma unroll
            for (int r = 0; r < 4; r++) acc[mt][nt][r] = 0;

    auto load_stage = [&](int c) {
        const int j0 = c * 32;
        const uint32_t st = sb + (uint32_t)(c & 1) * STAGEQ;
#pragma unroll
        for (int r = 0; r < 2; r++) {                    // A: 2 x 128 rows x 32B
            const int i = r * 256 + tid;
            const int m = i >> 8, rem = i & 255;
            const int row = rem >> 1, qq = rem & 1;
            CP16(st + (uint32_t)(m * A_SECQ + row * ASTQ + qq * 16),
                 (m ? g_norm2q : g_normq) + (i0g + row) * 512 + j0 + qq * 16);
        }
#pragma unroll
        for (int r = 0; r < 2; r++) {                    // B: 4 planes x 64 t x 32B
            const int i = r * 256 + tid;
            const int tb = i >> 7, rem = i & 127;
            const int trow = rem >> 1, qq = rem & 1;
            CP16(st + (uint32_t)(A_BYTESQ + tb * B_SECQ + trow * ASTQ + qq * 16),
                 zbq[tb] + trow * 512 + j0 + qq * 16);
        }
        CP_COMMIT();
    };

    load_stage(0);

    for (int c = 0; c < NCHUNKQ; c++) {
        if (c + 1 < NCHUNKQ) { load_stage(c + 1); CP_WAIT1(); }
        else                 { CP_WAIT0(); }
        __syncthreads();

        const char* A = sm + (size_t)(c & 1) * STAGEQ;
        const char* Bp = A + A_BYTESQ;

        uint32_t bf[2][4][2];
#pragma unroll
        for (int m = 0; m < 2; m++) {
            const char* bt = Bp + (ocl * 2 + m) * B_SECQ;
#pragma unroll
            for (int nt = 0; nt < 4; nt++) {
                const int trow = th * 32 + nt * 8 + g;
                bf[m][nt][0] = *(const uint32_t*)(bt + trow * ASTQ + tg * 4);
                bf[m][nt][1] = *(const uint32_t*)(bt + trow * ASTQ + 16 + tg * 4);
            }
        }
#pragma unroll
        for (int mt = 0; mt < 4; mt++) {
#pragma unroll
            for (int m = 0; m < 2; m++) {
                const char* ap = A + m * A_SECQ + (wi * 64 + mt * 16 + g) * ASTQ;
                const uint32_t a0 = *(const uint32_t*)(ap + tg * 4);
                const uint32_t a1 = *(const uint32_t*)(ap + 8 * ASTQ + tg * 4);
                const uint32_t a2 = *(const uint32_t*)(ap + 16 + tg * 4);
                const uint32_t a3 = *(const uint32_t*)(ap + 8 * ASTQ + 16 + tg * 4);
#pragma unroll
                for (int nt = 0; nt < 4; nt++)
                    MMA_S8(acc[mt][nt], a0, a1, a2, a3, bf[m][nt][0], bf[m][nt][1]);
            }
        }
        __syncthreads();
    }

    // ---- epilogue: dequant (per-t scale) + RMW into out (holds Z0 + bias) --
    float* obase = out + (((size_t)(b * 64 + oc0 + ocl) * 512) + i0g + wi * 64) * 64;
#pragma unroll
    for (int mt = 0; mt < 4; mt++) {
#pragma unroll
        for (int nt = 0; nt < 4; nt++) {
            const int r0 = mt * 16 + g, t0 = th * 32 + nt * 8 + tg * 2;
            float2* p0 = (float2*)(obase + r0 * 64 + t0);
            float2 v0 = *p0;
            v0.x += zsv[nt][0] * (float)acc[mt][nt][0];
            v0.y += zsv[nt][1] * (float)acc[mt][nt][1];
            *p0 = v0;
            float2* p1 = (float2*)(obase + (r0 + 8) * 64 + t0);
            float2 v1 = *p1;
            v1.x += zsv[nt][0] * (float)acc[mt][nt][2];
            v1.y += zsv[nt][1] * (float)acc[mt][nt][3];
            *p1 = v1;
        }
    }
}

// ---------------------------------------------------------------------------
extern "C" void kernel_launch(void* const* d_in, const int* in_sizes, int n_in,
                              void* d_out, int out_size) {
    const float* x    = (const float*)d_in[0];   // (16, 64, 512, 64) f32
    const float* adj  = (const float*)d_in[1];   // (512, 512) f32
    const float* W    = (const float*)d_in[2];   // (64, 192) f32
    const float* bias = (const float*)d_in[3];   // (64,) f32
    float* out = (float*)d_out;                  // (16, 64, 512, 64) f32

    const int spmm_smem = 2 * STAGEQ;            // 49152
    cudaFuncSetAttribute(k_mix_f16, cudaFuncAttributeMaxDynamicSharedMemorySize, MIX_SMEM);
    cudaFuncSetAttribute(k_zq, cudaFuncAttributeMaxDynamicSharedMemorySize, ZQ_SMEM);
    cudaFuncSetAttribute(k_spmm_i8, cudaFuncAttributeMaxDynamicSharedMemorySize, spmm_smem);

    k_rownorm<<<N_, 256>>>(adj, W);
    k_norm2<<<dim3(32, 32), dim3(16, 16)>>>();
    k_nq<<<N_, 256>>>();
    k_mix_f16<<<dim3(128, 2, 16), 256, MIX_SMEM>>>(x, bias, out);
    k_zq<<<1024, 256, ZQ_SMEM>>>();
    k_spmm_i8<<<dim3(4, 32, 16), 256, spmm_smem>>>(out);
}

// round 17
// speedup vs baseline: 2.0130x; 2.0130x over previous
#include <cuda_runtime.h>
#include <cuda_fp16.h>
#include <cstdint>

#define B_  16
#define N_  512
#define T_  64
#define OC_ 64

// ---------------- scratch (device globals; no runtime allocation) ----------
__device__ __align__(16) float  g_norm  [N_ * N_];      // fp32 (k_norm2 input)
__device__ __align__(16) __half g_normh [N_ * N_];      // fp16 (spmm A)
__device__ __align__(16) __half g_norm2h[N_ * N_];      // fp16 (spmm A)
__device__ __align__(16) __half g_Z1h[B_ * OC_ * N_ * T_];
__device__ __align__(16) __half g_Z2h[B_ * OC_ * N_ * T_];
__device__ __align__(16) __half g_Whf[192 * 64];        // [gc][c] fp16

// ======================= helpers ===========================================
__device__ __forceinline__ uint32_t smem_u32(const void* p) {
    uint32_t a;
    asm("{ .reg .u64 t; cvta.to.shared.u64 t, %1; cvt.u32.u64 %0, t; }"
        : "=r"(a) : "l"(p));
    return a;
}

#define CP16(dst, src) \
    asm volatile("cp.async.cg.shared.global [%0], [%1], 16;" \
                 :: "r"(dst), "l"(src) : "memory")
#define CP_COMMIT()  asm volatile("cp.async.commit_group;" ::: "memory")
#define CP_WAIT1()   asm volatile("cp.async.wait_group 1;" ::: "memory")
#define CP_WAIT0()   asm volatile("cp.async.wait_group 0;" ::: "memory")

#define MMA_F16(c, a0, a1, a2, a3, b0, b1) \
    asm volatile("mma.sync.aligned.m16n8k16.row.col.f32.f16.f16.f32 " \
                 "{%0,%1,%2,%3}, {%4,%5,%6,%7}, {%8,%9}, {%0,%1,%2,%3};" \
                 : "+f"((c)[0]), "+f"((c)[1]), "+f"((c)[2]), "+f"((c)[3]) \
                 : "r"(a0), "r"(a1), "r"(a2), "r"(a3), "r"(b0), "r"(b1))

__device__ __forceinline__ void ldsm_x4(uint32_t* r, uint32_t addr) {
    asm volatile("ldmatrix.sync.aligned.m8n8.x4.shared.b16 {%0,%1,%2,%3}, [%4];"
                 : "=r"(r[0]), "=r"(r[1]), "=r"(r[2]), "=r"(r[3]) : "r"(addr));
}
__device__ __forceinline__ void ldsm_x4t(uint32_t* r, uint32_t addr) {
    asm volatile("ldmatrix.sync.aligned.m8n8.x4.trans.shared.b16 {%0,%1,%2,%3}, [%4];"
                 : "=r"(r[0]), "=r"(r[1]), "=r"(r[2]), "=r"(r[3]) : "r"(addr));
}

// ---------------- kernel 0a: row-normalized adjacency ----------------------
__global__ void k_rownorm(const float* __restrict__ adj) {
    const int i = blockIdx.x;
    __shared__ float red[256];
    float s = 0.f;
    for (int j = threadIdx.x; j < N_; j += 256) s += adj[i * N_ + j];
    red[threadIdx.x] = s;
    __syncthreads();
    for (int off = 128; off > 0; off >>= 1) {
        if (threadIdx.x < off) red[threadIdx.x] += red[threadIdx.x + off];
        __syncthreads();
    }
    const float inv = 1.0f / (red[0] + 1e-6f);
    for (int j = threadIdx.x; j < N_; j += 256) {
        const float v = adj[i * N_ + j] * inv;
        g_norm [i * N_ + j] = v;
        g_normh[i * N_ + j] = __float2half_rn(v);
    }
}

// ---------------- kernel 0b: norm2 = norm @ norm (fp16 store) --------------
__global__ void k_norm2() {
    __shared__ float As[16][16];
    __shared__ float Bs[16][17];
    const int i = blockIdx.y * 16 + threadIdx.y;
    const int j = blockIdx.x * 16 + threadIdx.x;
    float acc = 0.f;
    for (int k0 = 0; k0 < N_; k0 += 16) {
        As[threadIdx.y][threadIdx.x] = g_norm[i * N_ + k0 + threadIdx.x];
        Bs[threadIdx.y][threadIdx.x] = g_norm[(k0 + threadIdx.y) * N_ + j];
        __syncthreads();
#pragma unroll
        for (int k = 0; k < 16; k++) acc += As[threadIdx.y][k] * Bs[k][threadIdx.x];
        __syncthreads();
    }
    g_norm2h[i * N_ + j] = __float2half_rn(acc);
}

// ---------------- kernel 0c: W -> fp16 [gc][c] layout -----------------------
__global__ void k_wt(const float* __restrict__ W) {
    const int idx = blockIdx.x * 256 + threadIdx.x;     // idx = gc*64 + c
    if (idx < 192 * 64) {
        const int gc = idx >> 6, c = idx & 63;
        const int grp = gc >> 6, oc = gc & 63;
        g_Whf[idx] = __float2half_rn(W[oc * 192 + grp * 64 + c]);
    }
}

// ---------------- kernel 1: channel mix via fp16 tensor cores ---------------
// CTA = (n4, cn, b). GEMM: M=256 (4n x 64t), N=96 (half of 192), K=64.
// Xh smem [c][m] halves (A via ldmatrix.trans); Wh [gc'][c] (B non-trans).
// Z0+bias (fp32) -> out; Z1/Z2 (fp16 RN) -> scratch.
#define XHST 264                               // Xh stride (halves)
#define WHST 72                                // Wh stride (halves)
#define SST  260
#define MIX_SMEM 49920                         // max(47616 data, 48*260*4 epi)

__global__ __launch_bounds__(256, 2) void k_mix_f16(const float* __restrict__ x,
                                                    const float* __restrict__ bias,
                                                    float* __restrict__ out) {
    extern __shared__ char dsm[];
    __half* Xh = (__half*)dsm;                       // [c=64][m=256]
    const uint32_t sb = smem_u32(dsm);
    const uint32_t wOff = 64 * XHST * 2;             // 33792
    const int n0 = blockIdx.x * 4, cn = blockIdx.y, b = blockIdx.z;
    const int tid = threadIdx.x, wid = tid >> 5, lane = tid & 31;
    const int u = wid >> 2, wi = wid & 3;
    const int g = lane >> 2, tg = lane & 3;
    const int q = lane >> 3, rr = lane & 7;

    // ---- W tile: 96 gc x 64 c halves via cp.async ----
#pragma unroll
    for (int r = 0; r < 3; r++) {
        const int i = r * 256 + tid;                 // < 768
        const int gcr = i >> 3, qq = i & 7;
        CP16(sb + wOff + (uint32_t)(gcr * WHST + qq * 8) * 2,
             g_Whf + (cn * 96 + gcr) * 64 + qq * 8);
    }
    CP_COMMIT();

    // ---- X tile: 64c x 256m fp32 -> fp16, [c][m] ----
#pragma unroll
    for (int r = 0; r < 16; r++) {
        const int i = r * 256 + tid;
        const int c = i >> 6, chunk = i & 63;
        const int nl = chunk >> 4, tq = chunk & 15;
        const float4 v = *(const float4*)(x + ((b * 64 + c) * 512 + n0 + nl) * 64 + tq * 4);
        union { __half2 h[2]; uint2 u2; } cv;
        cv.h[0] = __floats2half2_rn(v.x, v.y);
        cv.h[1] = __floats2half2_rn(v.z, v.w);
        *(uint2*)(Xh + c * XHST + nl * 64 + tq * 4) = cv.u2;
    }

    float acc[4][6][4];
#pragma unroll
    for (int mt = 0; mt < 4; mt++)
#pragma unroll
        for (int nt = 0; nt < 6; nt++)
#pragma unroll
            for (int r = 0; r < 4; r++) acc[mt][nt][r] = 0.f;

    CP_WAIT0();
    __syncthreads();

    // ---- mainloop: K=64 = 4 k16-steps ----
#pragma unroll
    for (int ks = 0; ks < 4; ks++) {
        uint32_t bf[3][4];
#pragma unroll
        for (int ntp = 0; ntp < 3; ntp++) {
            const int rowB = u * 48 + ntp * 16 + (q >> 1) * 8 + rr;   // gc
            const int colB = ks * 16 + (q & 1) * 8;                   // c
            ldsm_x4(bf[ntp], sb + wOff + (uint32_t)(rowB * WHST + colB) * 2);
        }
#pragma unroll
        for (int mt = 0; mt < 4; mt++) {
            const int rowA = ks * 16 + (q >> 1) * 8 + rr;             // c
            const int colA = wi * 64 + mt * 16 + (q & 1) * 8;         // m
            uint32_t af[4];
            ldsm_x4t(af, sb + (uint32_t)(rowA * XHST + colA) * 2);
#pragma unroll
            for (int nt = 0; nt < 6; nt++)
                MMA_F16(acc[mt][nt], af[0], af[1], af[2], af[3],
                        bf[nt >> 1][(nt & 1) * 2], bf[nt >> 1][(nt & 1) * 2 + 1]);
        }
    }

    // ---- epilogue: 2 passes through smem transpose Ss[oc'][m] ----
    float* Ss = (float*)dsm;
#pragma unroll
    for (int up = 0; up < 2; up++) {
        __syncthreads();
        if (u == up) {
#pragma unroll
            for (int mt = 0; mt < 4; mt++) {
                const int row = wi * 64 + mt * 16 + g;
#pragma unroll
                for (int nt = 0; nt < 6; nt++) {
                    const int col = nt * 8 + tg * 2;
                    Ss[col * SST + row]           = acc[mt][nt][0];
                    Ss[(col + 1) * SST + row]     = acc[mt][nt][1];
                    Ss[col * SST + row + 8]       = acc[mt][nt][2];
                    Ss[(col + 1) * SST + row + 8] = acc[mt][nt][3];
                }
            }
        }
        __syncthreads();
#pragma unroll
        for (int r = 0; r < 12; r++) {
            const int idx = r * 256 + tid;
            const int ocl = idx >> 6, mq = idx & 63;
            float4 v = *(const float4*)(Ss + ocl * SST + mq * 4);
            const int gc = cn * 96 + up * 48 + ocl;
            const int grp = gc >> 6, oc = gc & 63;
            const int base = ((b * 64 + oc) * 512 + n0 + (mq >> 4)) * 64 + (mq & 15) * 4;
            if (grp == 0) {
                const float bv = __ldg(bias + oc);
                v.x += bv; v.y += bv; v.z += bv; v.w += bv;
                *(float4*)(out + base) = v;
            } else {
                __half* dst = (grp == 1) ? g_Z1h : g_Z2h;
                union { __half2 h[2]; uint2 u2; } cv;
                cv.h[0] = __floats2half2_rn(v.x, v.y);
                cv.h[1] = __floats2half2_rn(v.z, v.w);
                *(uint2*)(dst + base) = cv.u2;
            }
        }
    }
}

// ---------------- kernel 2: out += norm@Z1 + norm2@Z2 (fp16 mma) -----------
// CTA = 128i x 64t x 2oc, 256 thr / 8 warps, 2 CTAs/SM.
// Warp = (wi: 2 x 64i) x (u: ocl = u>>1, t-half th = u&1) -> 64i x 32t.
// Kc=32, 2-stage cp.async; A stride 80B, B stride 144B (conflict-free ldsm).
#define AHST 40                                // A smem stride (halves)
#define BHST 72                                // B smem stride (halves)
#define A_SEC   (128 * AHST * 2)               // 10240 per matrix
#define A_BYTES (2 * A_SEC)                    // 20480
#define B_TILE  (32 * BHST * 2)                // 4608
#define STAGE   (A_BYTES + 4 * B_TILE)         // 38912
#define NCHUNK  16

__global__ __launch_bounds__(256, 2) void k_spmm_mma(float* __restrict__ out) {
    extern __shared__ char sm[];
    const uint32_t sb = smem_u32(sm);
    const int tid = threadIdx.x, wid = tid >> 5, lane = tid & 31;
    const int ih = blockIdx.x, ocp = blockIdx.y, b = blockIdx.z;
    const int i0g = ih * 128, oc0 = ocp * 2;
    const int wi = wid & 1, u = wid >> 1;
    const int ocl = u >> 1, th = u & 1;
    const int g = lane >> 2, tg = lane & 3;
    const int q = lane >> 3, rr = lane & 7;

    const __half* zb[4];
    zb[0] = g_Z1h + (size_t)(b * 64 + oc0) * 32768;
    zb[1] = g_Z2h + (size_t)(b * 64 + oc0) * 32768;
    zb[2] = g_Z1h + (size_t)(b * 64 + oc0 + 1) * 32768;
    zb[3] = g_Z2h + (size_t)(b * 64 + oc0 + 1) * 32768;

    float acc[4][4][4];
#pragma unroll
    for (int mt = 0; mt < 4; mt++)
#pragma unroll
        for (int nt = 0; nt < 4; nt++)
#pragma unroll
            for (int r = 0; r < 4; r++) acc[mt][nt][r] = 0.f;

    auto load_stage = [&](int c) {
        const int j0 = c * 32;
        const uint32_t st = sb + (uint32_t)(c & 1) * STAGE;
#pragma unroll
        for (int r = 0; r < 4; r++) {                    // A: 2 x 128 x 32h
            const int i = r * 256 + tid;
            const int m = i >> 9, rem = i & 511;
            const int row = rem >> 2, qq = rem & 3;
            CP16(st + (uint32_t)(m * A_SEC + row * (AHST * 2) + qq * 16),
                 (m ? g_norm2h : g_normh) + (i0g + row) * 512 + j0 + qq * 8);
        }
#pragma unroll
        for (int r = 0; r < 4; r++) {                    // B: 4 x 32 x 64h
            const int i = r * 256 + tid;
            const int tb = i >> 8, rem = i & 255;
            const int j = rem >> 3, qq = rem & 7;
            CP16(st + (uint32_t)(A_BYTES + tb * B_TILE + j * (BHST * 2) + qq * 16),
                 zb[tb] + (j0 + j) * 64 + qq * 8);
        }
        CP_COMMIT();
    };

    load_stage(0);

    for (int c = 0; c < NCHUNK; c++) {
        if (c + 1 < NCHUNK) { load_stage(c + 1); CP_WAIT1(); }
        else                { CP_WAIT0(); }
        __syncthreads();

        const uint32_t aA = sb + (uint32_t)(c & 1) * STAGE;
        const uint32_t aB = aA + A_BYTES;

#pragma unroll
        for (int ks = 0; ks < 2; ks++) {
            uint32_t bf[2][2][4];
#pragma unroll
            for (int m = 0; m < 2; m++) {
#pragma unroll
                for (int ntp = 0; ntp < 2; ntp++) {
                    const int rowB = ks * 16 + (q & 1) * 8 + rr;
                    const int colB = th * 32 + ntp * 16 + (q >> 1) * 8;
                    ldsm_x4t(bf[m][ntp],
                             aB + (uint32_t)((ocl * 2 + m) * 32 * BHST + rowB * BHST + colB) * 2);
                }
            }
#pragma unroll
            for (int mt = 0; mt < 4; mt++) {
#pragma unroll
                for (int m = 0; m < 2; m++) {
                    const int rowA = wi * 64 + mt * 16 + (q & 1) * 8 + rr;
                    const int colA = ks * 16 + (q >> 1) * 8;
                    uint32_t af[4];
                    ldsm_x4(af, aA + (uint32_t)(m * 128 * AHST + rowA * AHST + colA) * 2);
#pragma unroll
                    for (int nt = 0; nt < 4; nt++)
                        MMA_F16(acc[mt][nt], af[0], af[1], af[2], af[3],
                                bf[m][nt >> 1][(nt & 1) * 2],
                                bf[m][nt >> 1][(nt & 1) * 2 + 1]);
                }
            }
        }
        __syncthreads();
    }

    // ---- epilogue: RMW into out (holds Z0 + bias, fp32) ----
    float* obase = out + (((size_t)(b * 64 + oc0 + ocl) * 512) + i0g + wi * 64) * 64;
#pragma unroll
    for (int mt = 0; mt < 4; mt++) {
#pragma unroll
        for (int nt = 0; nt < 4; nt++) {
            const int r0 = mt * 16 + g, t0 = th * 32 + nt * 8 + tg * 2;
            float2* p0 = (float2*)(obase + r0 * 64 + t0);
            float2 v0 = *p0;
            v0.x += acc[mt][nt][0]; v0.y += acc[mt][nt][1];
            *p0 = v0;
            float2* p1 = (float2*)(obase + (r0 + 8) * 64 + t0);
            float2 v1 = *p1;
            v1.x += acc[mt][nt][2]; v1.y += acc[mt][nt][3];
            *p1 = v1;
        }
    }
}

// ---------------------------------------------------------------------------
extern "C" void kernel_launch(void* const* d_in, const int* in_sizes, int n_in,
                              void* d_out, int out_size) {
    const float* x    = (const float*)d_in[0];   // (16, 64, 512, 64) f32
    const float* adj  = (const float*)d_in[1];   // (512, 512) f32
    const float* W    = (const float*)d_in[2];   // (64, 192) f32
    const float* bias = (const float*)d_in[3];   // (64,) f32
    float* out = (float*)d_out;                  // (16, 64, 512, 64) f32

    const int spmm_smem = 2 * STAGE;             // 77824
    cudaFuncSetAttribute(k_mix_f16, cudaFuncAttributeMaxDynamicSharedMemorySize, MIX_SMEM);
    cudaFuncSetAttribute(k_spmm_mma, cudaFuncAttributeMaxDynamicSharedMemorySize, spmm_smem);

    k_rownorm<<<N_, 256>>>(adj);
    k_norm2<<<dim3(32, 32), dim3(16, 16)>>>();
    k_wt<<<48, 256>>>(W);
    k_mix_f16<<<dim3(128, 2, 16), 256, MIX_SMEM>>>(x, bias, out);
    k_spmm_mma<<<dim3(4, 32, 16), 256, spmm_smem>>>(out);
}